// round 1
// baseline (speedup 1.0000x reference)
#include <cuda_runtime.h>
#include <math.h>

// Problem constants
#define NVOX 32768          // 32*32*32 voxels
#define NC   64             // channels
#define DIMS 32
#define DP   34             // padded dim
#define GC   32             // channels per group
#define NG   2              // groups
#define NP   27             // kernel points
#define NOFF 162            // G*P*3
#define NMSK 54             // G*P
#define VOLG (DP*DP*DP*GC)  // per-group padded volume floats = 1257728
#define PADVOL (NG*VOLG)    // 2515456 floats
#define K1_BLOCKS (128*64)  // kernel1 grid blocks

// ---- scratch (static device allocations; allowed) ----
__device__ float g_xc[NVOX*NC];      // depthwise conv out, voxel-major [v][c]
__device__ float g_xt[NVOX*NC];      // input transposed, voxel-major [v][c]
__device__ float g_xpad[PADVOL];     // padded projected volume [g][z][y][x][gc]
__device__ float g_off[NVOX*NOFF];   // offsets [v][g*81 + p*3 + comp]
__device__ float g_mask[NVOX*NMSK];  // softmaxed masks [v][g*27+p]
__device__ float g_part[K1_BLOCKS*2];// per-block (sum, sumsq)
__device__ float g_stats[2];         // mean, rstd

// ---------------------------------------------------------------------------
// Kernel 0: zero the padded volume (border must be zero every launch)
// ---------------------------------------------------------------------------
__global__ void k_zero() {
    int i = blockIdx.x * blockDim.x + threadIdx.x;
    int n = PADVOL / 4;
    if (i < n) reinterpret_cast<float4*>(g_xpad)[i] = make_float4(0.f, 0.f, 0.f, 0.f);
}

// ---------------------------------------------------------------------------
// Kernel 1: depthwise 3x3x3 conv (pad 1) + transpose x to voxel-major
//           + per-block sum/sumsq partials for GroupNorm(1)
// grid (128, 64): blockIdx.y = channel, 256 voxels per block
// ---------------------------------------------------------------------------
__global__ void k_dw(const float* __restrict__ x, const float* __restrict__ dw_w) {
    int c = blockIdx.y;
    int v = blockIdx.x * 256 + threadIdx.x;
    int iz = v >> 10, iy = (v >> 5) & 31, ix = v & 31;
    const float* xs = x + c * NVOX;

    float w[27];
#pragma unroll
    for (int k = 0; k < 27; k++) w[k] = __ldg(dw_w + c * 27 + k);

    float acc = 0.f;
#pragma unroll
    for (int kz = 0; kz < 3; kz++) {
        int z = iz + kz - 1;
        if ((unsigned)z < 32u) {
#pragma unroll
            for (int ky = 0; ky < 3; ky++) {
                int y = iy + ky - 1;
                if ((unsigned)y < 32u) {
#pragma unroll
                    for (int kx = 0; kx < 3; kx++) {
                        int xx = ix + kx - 1;
                        if ((unsigned)xx < 32u)
                            acc = fmaf(w[kz*9 + ky*3 + kx], xs[(z << 10) + (y << 5) + xx], acc);
                    }
                }
            }
        }
    }
    g_xc[v * NC + c] = acc;
    g_xt[v * NC + c] = xs[v];

    // deterministic block reduction of (sum, sumsq)
    float s = acc, s2 = acc * acc;
#pragma unroll
    for (int o = 16; o > 0; o >>= 1) {
        s  += __shfl_down_sync(0xffffffffu, s,  o);
        s2 += __shfl_down_sync(0xffffffffu, s2, o);
    }
    __shared__ float sh[8][2];
    int lane = threadIdx.x & 31, wid = threadIdx.x >> 5;
    if (lane == 0) { sh[wid][0] = s; sh[wid][1] = s2; }
    __syncthreads();
    if (threadIdx.x == 0) {
        float S = 0.f, S2 = 0.f;
#pragma unroll
        for (int i = 0; i < 8; i++) { S += sh[i][0]; S2 += sh[i][1]; }
        int bid = blockIdx.y * gridDim.x + blockIdx.x;
        g_part[bid * 2]     = S;
        g_part[bid * 2 + 1] = S2;
    }
}

// ---------------------------------------------------------------------------
// Kernel 2: finalize mean / rstd (single block, deterministic)
// ---------------------------------------------------------------------------
__global__ void k_stats() {
    int tid = threadIdx.x;
    float s = 0.f, s2 = 0.f;
    for (int i = tid; i < K1_BLOCKS; i += 256) {
        s  += g_part[2 * i];
        s2 += g_part[2 * i + 1];
    }
#pragma unroll
    for (int o = 16; o > 0; o >>= 1) {
        s  += __shfl_down_sync(0xffffffffu, s,  o);
        s2 += __shfl_down_sync(0xffffffffu, s2, o);
    }
    __shared__ float sh[8][2];
    int lane = tid & 31, wid = tid >> 5;
    if (lane == 0) { sh[wid][0] = s; sh[wid][1] = s2; }
    __syncthreads();
    if (tid == 0) {
        float S = 0.f, S2 = 0.f;
#pragma unroll
        for (int i = 0; i < 8; i++) { S += sh[i][0]; S2 += sh[i][1]; }
        float n   = (float)(NVOX * NC);
        float mu  = S / n;
        float var = S2 / n - mu * mu;
        g_stats[0] = mu;
        g_stats[1] = rsqrtf(var + 1e-5f);
    }
}

// ---------------------------------------------------------------------------
// Kernel 3: per-voxel GN + tanh-GELU, then 3 pointwise GEMMs
//           offset (64->162), mask (64->54, +softmax per group),
//           xp (64->64, written directly into padded volume).
// 4 voxels per block (reuse each weight load for 4 FMAs), 256 threads.
// ---------------------------------------------------------------------------
__global__ void k_point(const float* __restrict__ gn_w,  const float* __restrict__ gn_b,
                        const float* __restrict__ inp_w, const float* __restrict__ inp_b,
                        const float* __restrict__ off_w, const float* __restrict__ off_b,
                        const float* __restrict__ mask_w,const float* __restrict__ mask_b) {
    int v0 = blockIdx.x * 4;
    int tid = threadIdx.x;
    __shared__ float s_x1[4][NC];
    __shared__ float s_xr[4][NC];
    __shared__ float s_m[4][NMSK];

    float mu = g_stats[0], rstd = g_stats[1];
    {
        int vv = tid >> 6, c = tid & 63;
        float xv = g_xc[(v0 + vv) * NC + c];
        float xn = (xv - mu) * rstd * gn_w[c] + gn_b[c];
        // tanh-approx GELU (jax.nn.gelu default)
        float t = tanhf(0.7978845608028654f * (xn + 0.044715f * xn * xn * xn));
        s_x1[vv][c] = 0.5f * xn * (1.f + t);
        s_xr[vv][c] = g_xt[(v0 + vv) * NC + c];
    }
    __syncthreads();

    for (int j = tid; j < NOFF + NMSK + NC; j += 256) {
        if (j < NOFF) {
            float b = off_b[j];
            float a0 = b, a1 = b, a2 = b, a3 = b;
            const float* wp = off_w + j;
#pragma unroll 8
            for (int c = 0; c < NC; c++) {
                float w = wp[c * NOFF];
                a0 = fmaf(s_x1[0][c], w, a0); a1 = fmaf(s_x1[1][c], w, a1);
                a2 = fmaf(s_x1[2][c], w, a2); a3 = fmaf(s_x1[3][c], w, a3);
            }
            g_off[(v0 + 0) * NOFF + j] = a0; g_off[(v0 + 1) * NOFF + j] = a1;
            g_off[(v0 + 2) * NOFF + j] = a2; g_off[(v0 + 3) * NOFF + j] = a3;
        } else if (j < NOFF + NMSK) {
            int m = j - NOFF;
            float b = mask_b[m];
            float a0 = b, a1 = b, a2 = b, a3 = b;
            const float* wp = mask_w + m;
#pragma unroll 8
            for (int c = 0; c < NC; c++) {
                float w = wp[c * NMSK];
                a0 = fmaf(s_x1[0][c], w, a0); a1 = fmaf(s_x1[1][c], w, a1);
                a2 = fmaf(s_x1[2][c], w, a2); a3 = fmaf(s_x1[3][c], w, a3);
            }
            s_m[0][m] = a0; s_m[1][m] = a1; s_m[2][m] = a2; s_m[3][m] = a3;
        } else {
            int o = j - NOFF - NMSK;
            float b = inp_b[o];
            float a0 = b, a1 = b, a2 = b, a3 = b;
            const float* wp = inp_w + o;
#pragma unroll 8
            for (int c = 0; c < NC; c++) {
                float w = wp[c * NC];
                a0 = fmaf(s_xr[0][c], w, a0); a1 = fmaf(s_xr[1][c], w, a1);
                a2 = fmaf(s_xr[2][c], w, a2); a3 = fmaf(s_xr[3][c], w, a3);
            }
            int g = o >> 5, ch = o & 31;
            float av[4] = {a0, a1, a2, a3};
#pragma unroll
            for (int vv = 0; vv < 4; vv++) {
                int v = v0 + vv;
                int iz = v >> 10, iy = (v >> 5) & 31, ix = v & 31;
                int idx = ((((g * DP + iz + 1) * DP + iy + 1) * DP + ix + 1) << 5) + ch;
                g_xpad[idx] = av[vv];
            }
        }
    }
    __syncthreads();

    // per (voxel, group) softmax over 27 points
    if (tid < 8) {
        int vv = tid >> 1, gi = tid & 1;
        float mx = -1e30f;
#pragma unroll
        for (int p = 0; p < NP; p++) mx = fmaxf(mx, s_m[vv][gi * NP + p]);
        float s = 0.f;
#pragma unroll
        for (int p = 0; p < NP; p++) s += expf(s_m[vv][gi * NP + p] - mx);
        float inv = 1.f / s;
#pragma unroll
        for (int p = 0; p < NP; p++)
            g_mask[(v0 + vv) * NMSK + gi * NP + p] = expf(s_m[vv][gi * NP + p] - mx) * inv;
    }
}

// ---------------------------------------------------------------------------
// Kernel 4: deformable trilinear sampling + masked accumulate + output GEMM.
// 4 voxels per block, 64 threads. Thread layout:
//   vv = tid/16, group = (tid/8)&1, c4 = tid&7 (owns 4 channels via float4)
// Each tap: 1 LDG.128 + 4 FMA; taps 128B-coalesced across the 8 group lanes.
// ---------------------------------------------------------------------------
__global__ void k_sample(const float* __restrict__ out_w, const float* __restrict__ out_b,
                         float* __restrict__ out) {
    int v0 = blockIdx.x * 4;
    int tid = threadIdx.x;
    __shared__ float s_off[4 * NOFF];
    __shared__ float s_m[4 * NMSK];
    __shared__ float s_acc[4][NC];

    for (int j = tid; j < 4 * NOFF; j += 64) s_off[j] = g_off[v0 * NOFF + j];
    for (int j = tid; j < 4 * NMSK; j += 64) s_m[j]   = g_mask[v0 * NMSK + j];
    __syncthreads();

    int vv = tid >> 4;
    int gi = (tid >> 3) & 1;
    int c4 = tid & 7;
    int v = v0 + vv;
    int iz = v >> 10, iy = (v >> 5) & 31, ix = v & 31;

    const float4* vol = reinterpret_cast<const float4*>(g_xpad) + gi * (VOLG / 4) + c4;
    const float* offp = s_off + vv * NOFF + gi * (NP * 3);
    const float* mp   = s_m + vv * NMSK + gi * NP;

    float4 acc = make_float4(0.f, 0.f, 0.f, 0.f);
    for (int p = 0; p < NP; p++) {
        float ox = offp[p * 3 + 0];
        float oy = offp[p * 3 + 1];
        float oz = offp[p * 3 + 2];
        // padded-volume sample coords (derived from reference grid math):
        // s = out_idx + 1 + (k-1) + axis_scale*0.5*off = out_idx + k + scaled off
        float sx = (float)(ix + (p % 3))       + 0.25f * ox;
        float sy = (float)(iy + ((p / 3) % 3)) + 0.5f  * oy;
        float sz = (float)(iz + (p / 9))       + 0.5f  * oz;
        float xf = floorf(sx), yf = floorf(sy), zf = floorf(sz);
        int x0 = (int)xf, y0 = (int)yf, z0 = (int)zf;
        float fx = sx - xf, fy = sy - yf, fz = sz - zf;

        float4 smp = make_float4(0.f, 0.f, 0.f, 0.f);
#pragma unroll
        for (int dz = 0; dz < 2; dz++) {
            int cz = z0 + dz;
            if ((unsigned)cz >= (unsigned)DP) continue;
            float wz = dz ? fz : 1.f - fz;
#pragma unroll
            for (int dy = 0; dy < 2; dy++) {
                int cy = y0 + dy;
                if ((unsigned)cy >= (unsigned)DP) continue;
                float wy = dy ? fy : 1.f - fy;
#pragma unroll
                for (int dx = 0; dx < 2; dx++) {
                    int cx = x0 + dx;
                    if ((unsigned)cx >= (unsigned)DP) continue;
                    float w = wz * wy * ((dx) ? fx : 1.f - fx);
                    float4 val = vol[((cz * DP + cy) * DP + cx) << 3];
                    smp.x = fmaf(w, val.x, smp.x);
                    smp.y = fmaf(w, val.y, smp.y);
                    smp.z = fmaf(w, val.z, smp.z);
                    smp.w = fmaf(w, val.w, smp.w);
                }
            }
        }
        float m = mp[p];
        acc.x = fmaf(m, smp.x, acc.x);
        acc.y = fmaf(m, smp.y, acc.y);
        acc.z = fmaf(m, smp.z, acc.z);
        acc.w = fmaf(m, smp.w, acc.w);
    }

    int ch = gi * GC + c4 * 4;
    s_acc[vv][ch + 0] = acc.x;
    s_acc[vv][ch + 1] = acc.y;
    s_acc[vv][ch + 2] = acc.z;
    s_acc[vv][ch + 3] = acc.w;
    __syncthreads();

    // output projection: thread tid = output channel, weight reused x4 voxels
    float b = out_b[tid];
    float o0 = b, o1 = b, o2 = b, o3 = b;
#pragma unroll 8
    for (int c = 0; c < NC; c++) {
        float w = out_w[c * NC + tid];
        o0 = fmaf(s_acc[0][c], w, o0);
        o1 = fmaf(s_acc[1][c], w, o1);
        o2 = fmaf(s_acc[2][c], w, o2);
        o3 = fmaf(s_acc[3][c], w, o3);
    }
    out[(v0 + 0) * NC + tid] = o0;
    out[(v0 + 1) * NC + tid] = o1;
    out[(v0 + 2) * NC + tid] = o2;
    out[(v0 + 3) * NC + tid] = o3;
}

// ---------------------------------------------------------------------------
extern "C" void kernel_launch(void* const* d_in, const int* in_sizes, int n_in,
                              void* d_out, int out_size) {
    const float* x      = (const float*)d_in[0];
    const float* dw_w   = (const float*)d_in[1];
    const float* gn_w   = (const float*)d_in[2];
    const float* gn_b   = (const float*)d_in[3];
    const float* inp_w  = (const float*)d_in[4];
    const float* inp_b  = (const float*)d_in[5];
    const float* off_w  = (const float*)d_in[6];
    const float* off_b  = (const float*)d_in[7];
    const float* mask_w = (const float*)d_in[8];
    const float* mask_b = (const float*)d_in[9];
    const float* out_w  = (const float*)d_in[10];
    const float* out_b  = (const float*)d_in[11];
    float* out = (float*)d_out;

    k_zero<<<(PADVOL / 4 + 255) / 256, 256>>>();
    k_dw<<<dim3(128, 64), 256>>>(x, dw_w);
    k_stats<<<1, 256>>>();
    k_point<<<NVOX / 4, 256>>>(gn_w, gn_b, inp_w, inp_b, off_w, off_b, mask_w, mask_b);
    k_sample<<<NVOX / 4, 64>>>(out_w, out_b, out);
}